// round 5
// baseline (speedup 1.0000x reference)
#include <cuda_runtime.h>
#include <cstddef>

// ---------------------------------------------------------------------------
// RGCN: 5 x HeteroGraphConv (R=3 relations, norm='both', mean cross-relation)
//       + LeakyReLU(0.01) after layers 0..3, + final Linear 128->64.
//
// Structure per layer:
//   1) scatter: AGG[dst, r*128+d] += h[src,d] * invsqrt(outdeg_r[src]) * invsqrt(indeg_r[dst])
//      (both GCN norms folded into the per-edge scalar; warp-per-edge,
//       red.global.add.v4.f32 — 4x fewer atomic ops than scalar atomicAdd)
//   2) GEMM: H' = (1/3) * AGG[N,384] @ Wcat[384,128] + mean_bias ; optional leaky-relu
//      (Wcat IS the raw W0 / Wl[l] tensor reinterpreted [R*128,128] row-major —
//       its (r,k) row order matches AGG's column order, so no repack needed)
//
// Degrees depend only on the edge lists -> computed once per launch.
// ---------------------------------------------------------------------------

#define NNODES 50000
#define DHID   128
#define DOUT   64
#define NREL   3
#define NEDGE  800000
#define NEG_SLOPE 0.01f

// -------- static device scratch (no allocations allowed) -------------------
__device__ float g_H[2][(size_t)NNODES * DHID];            // ping-pong hidden (2 x 25.6 MB)
__device__ float g_AGG[(size_t)NNODES * NREL * DHID];      // stacked aggregates (76.8 MB)
__device__ int   g_deg[2 * NREL * NNODES];                 // [0..R*N): out-deg, [R*N..): in-deg
__device__ float g_inv[2 * NREL * NNODES];                 // rsqrt(max(deg,1))

// ---------------------------------------------------------------------------
__global__ void deg_count_kernel(const int* __restrict__ esrc,
                                 const int* __restrict__ edst) {
    int i = blockIdx.x * blockDim.x + threadIdx.x;
    if (i >= NREL * NEDGE) return;
    int r = i / NEDGE;
    atomicAdd(&g_deg[r * NNODES + esrc[i]], 1);                       // out-degree (src)
    atomicAdd(&g_deg[NREL * NNODES + r * NNODES + edst[i]], 1);       // in-degree  (dst)
}

__global__ void deg_inv_kernel() {
    int i = blockIdx.x * blockDim.x + threadIdx.x;
    if (i >= 2 * NREL * NNODES) return;
    g_inv[i] = rsqrtf(fmaxf((float)g_deg[i], 1.0f));
}

// warp per edge: lanes cover the 128-float row as float4 (coalesced 512B read)
__global__ void scatter_kernel(const float* __restrict__ Hin,
                               const int* __restrict__ esrc,
                               const int* __restrict__ edst) {
    int w    = (blockIdx.x * blockDim.x + threadIdx.x) >> 5;
    int lane = threadIdx.x & 31;
    if (w >= NREL * NEDGE) return;
    int r   = w / NEDGE;
    int src = esrc[w];
    int dst = edst[w];
    float s = g_inv[r * NNODES + src] * g_inv[NREL * NNODES + r * NNODES + dst];

    const float4* hp = (const float4*)(Hin + (size_t)src * DHID);
    float4 v = hp[lane];
    v.x *= s; v.y *= s; v.z *= s; v.w *= s;

    float* dp = &g_AGG[(size_t)dst * (NREL * DHID) + r * DHID + lane * 4];
    asm volatile("red.global.add.v4.f32 [%0], {%1, %2, %3, %4};"
                 :: "l"(dp), "f"(v.x), "f"(v.y), "f"(v.z), "f"(v.w)
                 : "memory");
}

// ---------------------------------------------------------------------------
// fp32 SIMT GEMM: C[M,Nout] = scale * (A[M,K] @ W[K,Nout]) + scale*sum_r bias_r
// BM=64, BN=64, BK=16, 128 threads, thread microtile 8x4 (FMA-bound).
// ---------------------------------------------------------------------------
#define BM 64
#define BN 64
#define BK 16

__global__ __launch_bounds__(128)
void gemm_kernel(const float* __restrict__ A, int lda,
                 const float* __restrict__ W,     // [K, Nout] row-major
                 const float* __restrict__ bias,  // [biasR, Nout]
                 int biasR, float scale, int act,
                 int M, int K, int Nout,
                 float* __restrict__ C) {
    __shared__ float As[BK][BM];
    __shared__ float Bs[BK][BN];

    int t  = threadIdx.x;
    int tx = t & 15;    // 0..15 (n direction, TN=4)
    int ty = t >> 4;    // 0..7  (m direction, TM=8)
    int gm = blockIdx.y * BM;
    int gn = blockIdx.x * BN;

    // A-tile load mapping: each thread loads 8 contiguous k's of one m-row
    int am = t >> 1;            // 0..63
    int ak = (t & 1) * 8;       // 0 or 8
    // B-tile load mapping: each thread loads 8 contiguous n's of one k-row
    int bk = t >> 3;            // 0..15
    int bn = (t & 7) * 8;       // 0..56

    float acc[8][4];
#pragma unroll
    for (int i = 0; i < 8; i++)
#pragma unroll
        for (int j = 0; j < 4; j++) acc[i][j] = 0.0f;

    for (int k0 = 0; k0 < K; k0 += BK) {
        // ---- load A tile (guard M edge) ----
        float4 a0, a1;
        int row = gm + am;
        if (row < M) {
            const float* ap = A + (size_t)row * lda + k0 + ak;
            a0 = *(const float4*)ap;
            a1 = *(const float4*)(ap + 4);
        } else {
            a0 = make_float4(0.f, 0.f, 0.f, 0.f);
            a1 = a0;
        }
        As[ak + 0][am] = a0.x; As[ak + 1][am] = a0.y;
        As[ak + 2][am] = a0.z; As[ak + 3][am] = a0.w;
        As[ak + 4][am] = a1.x; As[ak + 5][am] = a1.y;
        As[ak + 6][am] = a1.z; As[ak + 7][am] = a1.w;

        // ---- load B tile (K multiple of 16, Nout multiple of 64: no guard) ----
        const float* wp = W + (size_t)(k0 + bk) * Nout + gn + bn;
        *(float4*)&Bs[bk][bn]     = *(const float4*)wp;
        *(float4*)&Bs[bk][bn + 4] = *(const float4*)(wp + 4);

        __syncthreads();

#pragma unroll
        for (int k = 0; k < BK; k++) {
            float a[8], b[4];
            *(float4*)&a[0] = *(const float4*)&As[k][ty * 8];
            *(float4*)&a[4] = *(const float4*)&As[k][ty * 8 + 4];
            *(float4*)&b[0] = *(const float4*)&Bs[k][tx * 4];
#pragma unroll
            for (int i = 0; i < 8; i++)
#pragma unroll
                for (int j = 0; j < 4; j++)
                    acc[i][j] = fmaf(a[i], b[j], acc[i][j]);
        }
        __syncthreads();
    }

    // ---- epilogue: scale, mean-bias, optional leaky-relu ----
    float bv[4];
#pragma unroll
    for (int j = 0; j < 4; j++) {
        float s = 0.0f;
        for (int rr = 0; rr < biasR; rr++)
            s += bias[(size_t)rr * Nout + gn + tx * 4 + j];
        bv[j] = s * scale;
    }
#pragma unroll
    for (int i = 0; i < 8; i++) {
        int row = gm + ty * 8 + i;
        if (row < M) {
            float4 o;
            o.x = acc[i][0] * scale + bv[0];
            o.y = acc[i][1] * scale + bv[1];
            o.z = acc[i][2] * scale + bv[2];
            o.w = acc[i][3] * scale + bv[3];
            if (act) {
                o.x = o.x > 0.f ? o.x : o.x * NEG_SLOPE;
                o.y = o.y > 0.f ? o.y : o.y * NEG_SLOPE;
                o.z = o.z > 0.f ? o.z : o.z * NEG_SLOPE;
                o.w = o.w > 0.f ? o.w : o.w * NEG_SLOPE;
            }
            *(float4*)&C[(size_t)row * Nout + gn + tx * 4] = o;
        }
    }
}

// ---------------------------------------------------------------------------
extern "C" void kernel_launch(void* const* d_in, const int* in_sizes, int n_in,
                              void* d_out, int out_size) {
    const float* x    = (const float*)d_in[0];   // [N, 128]
    const int*   esrc = (const int*)  d_in[1];   // [R, E]
    const int*   edst = (const int*)  d_in[2];   // [R, E]
    const float* W0   = (const float*)d_in[3];   // [R, 128, 128]
    const float* b0   = (const float*)d_in[4];   // [R, 128]
    const float* Wl   = (const float*)d_in[5];   // [4, R, 128, 128]
    const float* bl   = (const float*)d_in[6];   // [4, R, 128]
    const float* Wout = (const float*)d_in[7];   // [128, 64]
    const float* bout = (const float*)d_in[8];   // [64]
    float* out = (float*)d_out;
    (void)in_sizes; (void)n_in; (void)out_size;

    void *degp, *aggp, *hp;
    cudaGetSymbolAddress(&degp, g_deg);
    cudaGetSymbolAddress(&aggp, g_AGG);
    cudaGetSymbolAddress(&hp,   g_H);
    float* H0 = (float*)hp;
    float* H1 = H0 + (size_t)NNODES * DHID;

    // degrees: once per launch
    cudaMemsetAsync(degp, 0, sizeof(int) * 2 * NREL * NNODES, 0);
    deg_count_kernel<<<(NREL * NEDGE + 255) / 256, 256>>>(esrc, edst);
    deg_inv_kernel<<<(2 * NREL * NNODES + 255) / 256, 256>>>();

    const float* hin = x;
    for (int l = 0; l < 5; l++) {
        cudaMemsetAsync(aggp, 0, sizeof(float) * (size_t)NNODES * NREL * DHID, 0);

        // warp per edge -> R*E*32 threads
        long long nthreads = (long long)NREL * NEDGE * 32;
        scatter_kernel<<<(unsigned)((nthreads + 255) / 256), 256>>>(hin, esrc, edst);

        const float* Wlayer = (l == 0) ? W0 : Wl + (size_t)(l - 1) * NREL * DHID * DHID;
        const float* blayer = (l == 0) ? b0 : bl + (size_t)(l - 1) * NREL * DHID;
        float* hout = (l & 1) ? H1 : H0;

        dim3 grid(DHID / BN, (NNODES + BM - 1) / BM);
        gemm_kernel<<<grid, 128>>>((const float*)aggp, NREL * DHID,
                                   Wlayer, blayer, NREL, 1.0f / NREL,
                                   (l < 4) ? 1 : 0,
                                   NNODES, NREL * DHID, DHID, hout);
        hin = hout;
    }

    // final linear 128 -> 64
    dim3 grid(DOUT / BN, (NNODES + BM - 1) / BM);
    gemm_kernel<<<grid, 128>>>(hin, DHID, Wout, bout, 1, 1.0f, 0,
                               NNODES, DHID, DOUT, out);
}

// round 6
// speedup vs baseline: 1.7517x; 1.7517x over previous
#include <cuda_runtime.h>
#include <cstddef>

// ---------------------------------------------------------------------------
// RGCN, restructured as transform-then-gather per layer:
//   Y[n, r*128+j] = sum_k h[n,k] * W[r][k][j]                (GEMM, 3x391 grid)
//   H'[dst, j]    = leaky( (1/3) * sum_r sum_{e in CSR_r(dst)} scale_e * Y[src_e, r*128+j]
//                          + (1/3) * sum_r b_r[j] )          (CSR gather, no atomics)
// scale_e = rsqrt(max(outdeg_r[src],1)) * rsqrt(max(indeg_r[dst],1))  (norm='both')
// CSR (dst-sorted edges + per-edge scale) is built once per launch.
// ---------------------------------------------------------------------------

#define NNODES 50000
#define DHID   128
#define DOUT   64
#define NREL   3
#define NEDGE  800000
#define NW     (NREL * NNODES)      // 150000 CSR rows
#define NEG_SLOPE 0.01f

// -------- static device scratch ---------------------------------------------
__device__ float g_H[2][(size_t)NNODES * DHID];        // ping-pong hidden
__device__ float g_Y[(size_t)NNODES * NREL * DHID];    // transformed features [N,384]
__device__ int   g_deg[2 * NW];                        // [0..NW): out-deg, [NW..): in-deg
__device__ float g_inv[2 * NW];                        // rsqrt(max(deg,1))
__device__ int   g_rowptr[NW + 1];
__device__ int   g_cursor[NW];
__device__ int   g_bsums[256];
__device__ int   g_csr_src[NREL * NEDGE];
__device__ float g_csr_scale[NREL * NEDGE];

// ---------------------------------------------------------------------------
__global__ void deg_count_kernel(const int* __restrict__ esrc,
                                 const int* __restrict__ edst) {
    int i = blockIdx.x * blockDim.x + threadIdx.x;
    if (i >= NREL * NEDGE) return;
    int r = i / NEDGE;
    atomicAdd(&g_deg[r * NNODES + esrc[i]], 1);
    atomicAdd(&g_deg[NW + r * NNODES + edst[i]], 1);
}

__global__ void deg_inv_kernel() {
    int i = blockIdx.x * blockDim.x + threadIdx.x;
    if (i >= 2 * NW) return;
    g_inv[i] = rsqrtf(fmaxf((float)g_deg[i], 1.0f));
}

// ---- exclusive prefix-sum of in-degrees -> g_rowptr ------------------------
// scan1: 1024 items/block (256 thr x 4), per-block exclusive scan + block sums
__global__ void scan1_kernel() {
    __shared__ int sh[256];
    int t = threadIdx.x;
    int base = blockIdx.x * 1024 + t * 4;
    int v[4], s = 0;
#pragma unroll
    for (int j = 0; j < 4; j++) {
        int idx = base + j;
        v[j] = (idx < NW) ? g_deg[NW + idx] : 0;
        s += v[j];
    }
    sh[t] = s;
    __syncthreads();
    for (int off = 1; off < 256; off <<= 1) {
        int x = (t >= off) ? sh[t - off] : 0;
        __syncthreads();
        sh[t] += x;
        __syncthreads();
    }
    int run = sh[t] - s;   // exclusive within block
#pragma unroll
    for (int j = 0; j < 4; j++) {
        int idx = base + j;
        if (idx < NW) g_rowptr[idx] = run;
        run += v[j];
    }
    if (t == 255) g_bsums[blockIdx.x] = sh[255];
}

// scan2: single block scans block sums (nblocks <= 256), writes grand total
__global__ void scan2_kernel(int nblocks) {
    __shared__ int sh[256];
    int t = threadIdx.x;
    int v = (t < nblocks) ? g_bsums[t] : 0;
    sh[t] = v;
    __syncthreads();
    for (int off = 1; off < 256; off <<= 1) {
        int x = (t >= off) ? sh[t - off] : 0;
        __syncthreads();
        sh[t] += x;
        __syncthreads();
    }
    if (t < nblocks) g_bsums[t] = sh[t] - v;   // exclusive block offsets
    if (t == 255) g_rowptr[NW] = sh[255];      // total edge count
}

__global__ void scan3_kernel() {
    int i = blockIdx.x * blockDim.x + threadIdx.x;
    if (i >= NW) return;
    g_rowptr[i] += g_bsums[i >> 10];
}

// fill CSR: dst-sorted edge src ids + folded per-edge norm scale
__global__ void fill_kernel(const int* __restrict__ esrc,
                            const int* __restrict__ edst) {
    int i = blockIdx.x * blockDim.x + threadIdx.x;
    if (i >= NREL * NEDGE) return;
    int r = i / NEDGE;
    int src = esrc[i];
    int dst = edst[i];
    int w = r * NNODES + dst;
    int pos = atomicAdd(&g_cursor[w], 1);
    g_csr_src[pos]   = src;
    g_csr_scale[pos] = g_inv[r * NNODES + src] * g_inv[NW + w];
}

// ---------------------------------------------------------------------------
// Transform GEMM: Y[m, r*128+j] = sum_k A[m,k] * W[r][k][j]
// grid = (NREL, ceil(M/128)), 256 threads, 128x128x8 tiles, 8x8 microtile.
// ---------------------------------------------------------------------------
#define GBM 128
#define GBN 128
#define GBK 8

__global__ __launch_bounds__(256)
void gemm_transform(const float* __restrict__ A,   // [M, 128]
                    const float* __restrict__ W,   // [R, 128, 128]
                    float* __restrict__ Y) {       // [M, 384]
    __shared__ float As[GBK][GBM];
    __shared__ float Bs[GBK][GBN];

    int t  = threadIdx.x;
    int r  = blockIdx.x;
    int gm = blockIdx.y * GBM;
    const float* Wr = W + (size_t)r * DHID * DHID;

    int tx = t & 15;          // 0..15 (n), 8 cols each
    int ty = t >> 4;          // 0..15 (m), 8 rows each
    int am = t >> 1;          // A-load row 0..127
    int ak = (t & 1) * 4;     // A-load k quad
    int bkr = t >> 5;         // B-load k row 0..7
    int bnc = (t & 31) * 4;   // B-load n quad

    float acc[8][8];
#pragma unroll
    for (int i = 0; i < 8; i++)
#pragma unroll
        for (int j = 0; j < 8; j++) acc[i][j] = 0.0f;

    for (int k0 = 0; k0 < DHID; k0 += GBK) {
        int row = gm + am;
        float4 a;
        if (row < NNODES) a = *(const float4*)(A + (size_t)row * DHID + k0 + ak);
        else              a = make_float4(0.f, 0.f, 0.f, 0.f);
        As[ak + 0][am] = a.x; As[ak + 1][am] = a.y;
        As[ak + 2][am] = a.z; As[ak + 3][am] = a.w;

        *(float4*)&Bs[bkr][bnc] = *(const float4*)(Wr + (size_t)(k0 + bkr) * DHID + bnc);

        __syncthreads();
#pragma unroll
        for (int k = 0; k < GBK; k++) {
            float av[8], bv[8];
            *(float4*)&av[0] = *(const float4*)&As[k][ty * 8];
            *(float4*)&av[4] = *(const float4*)&As[k][ty * 8 + 4];
            *(float4*)&bv[0] = *(const float4*)&Bs[k][tx * 8];
            *(float4*)&bv[4] = *(const float4*)&Bs[k][tx * 8 + 4];
#pragma unroll
            for (int i = 0; i < 8; i++)
#pragma unroll
                for (int j = 0; j < 8; j++)
                    acc[i][j] = fmaf(av[i], bv[j], acc[i][j]);
        }
        __syncthreads();
    }

#pragma unroll
    for (int i = 0; i < 8; i++) {
        int row = gm + ty * 8 + i;
        if (row < NNODES) {
            float* yp = Y + (size_t)row * (NREL * DHID) + r * DHID + tx * 8;
            float4 o0, o1;
            o0.x = acc[i][0]; o0.y = acc[i][1]; o0.z = acc[i][2]; o0.w = acc[i][3];
            o1.x = acc[i][4]; o1.y = acc[i][5]; o1.z = acc[i][6]; o1.w = acc[i][7];
            *(float4*)yp       = o0;
            *(float4*)(yp + 4) = o1;
        }
    }
}

// ---------------------------------------------------------------------------
// CSR gather: warp per dst node; lane covers 4 cols (float4).
// H'[dst] = act( (1/3) * (sum_r sum_e scale_e * Y[src_e, r*128+*]) + bmean )
// ---------------------------------------------------------------------------
__global__ __launch_bounds__(256)
void gather_kernel(const float* __restrict__ Y,
                   const float* __restrict__ bias,  // [R, 128]
                   int act,
                   float* __restrict__ Hout) {
    int w    = (blockIdx.x * blockDim.x + threadIdx.x) >> 5;   // dst node
    int lane = threadIdx.x & 31;
    if (w >= NNODES) return;

    float4 acc = make_float4(0.f, 0.f, 0.f, 0.f);

#pragma unroll
    for (int r = 0; r < NREL; r++) {
        int row = r * NNODES + w;
        int e   = g_rowptr[row];
        int end = g_rowptr[row + 1];
        const float* Ybase = Y + r * DHID + lane * 4;

        // 2-edge software pipeline for MLP
        for (; e + 1 < end; e += 2) {
            int   s0 = g_csr_src[e],     s1 = g_csr_src[e + 1];
            float c0 = g_csr_scale[e],   c1 = g_csr_scale[e + 1];
            float4 v0 = *(const float4*)(Ybase + (size_t)s0 * (NREL * DHID));
            float4 v1 = *(const float4*)(Ybase + (size_t)s1 * (NREL * DHID));
            acc.x = fmaf(c0, v0.x, acc.x); acc.y = fmaf(c0, v0.y, acc.y);
            acc.z = fmaf(c0, v0.z, acc.z); acc.w = fmaf(c0, v0.w, acc.w);
            acc.x = fmaf(c1, v1.x, acc.x); acc.y = fmaf(c1, v1.y, acc.y);
            acc.z = fmaf(c1, v1.z, acc.z); acc.w = fmaf(c1, v1.w, acc.w);
        }
        if (e < end) {
            int   s0 = g_csr_src[e];
            float c0 = g_csr_scale[e];
            float4 v0 = *(const float4*)(Ybase + (size_t)s0 * (NREL * DHID));
            acc.x = fmaf(c0, v0.x, acc.x); acc.y = fmaf(c0, v0.y, acc.y);
            acc.z = fmaf(c0, v0.z, acc.z); acc.w = fmaf(c0, v0.w, acc.w);
        }
    }

    // mean over relations + mean bias
    float4 bm = make_float4(0.f, 0.f, 0.f, 0.f);
#pragma unroll
    for (int r = 0; r < NREL; r++) {
        float4 b = *(const float4*)(bias + r * DHID + lane * 4);
        bm.x += b.x; bm.y += b.y; bm.z += b.z; bm.w += b.w;
    }
    const float inv3 = 1.0f / NREL;
    float4 o;
    o.x = (acc.x + bm.x) * inv3;
    o.y = (acc.y + bm.y) * inv3;
    o.z = (acc.z + bm.z) * inv3;
    o.w = (acc.w + bm.w) * inv3;
    if (act) {
        o.x = o.x > 0.f ? o.x : o.x * NEG_SLOPE;
        o.y = o.y > 0.f ? o.y : o.y * NEG_SLOPE;
        o.z = o.z > 0.f ? o.z : o.z * NEG_SLOPE;
        o.w = o.w > 0.f ? o.w : o.w * NEG_SLOPE;
    }
    *(float4*)(Hout + (size_t)w * DHID + lane * 4) = o;
}

// ---------------------------------------------------------------------------
// Small fp32 GEMM for the final 128->64 linear (BM=64,BN=64,BK=16, 8x4 tile).
// ---------------------------------------------------------------------------
#define BM 64
#define BN 64
#define BK 16

__global__ __launch_bounds__(128)
void gemm_final(const float* __restrict__ A,      // [M, 128]
                const float* __restrict__ W,      // [128, 64]
                const float* __restrict__ bias,   // [64]
                int M, int K, int Nout,
                float* __restrict__ C) {
    __shared__ float As[BK][BM];
    __shared__ float Bs[BK][BN];

    int t  = threadIdx.x;
    int tx = t & 15;
    int ty = t >> 4;
    int gm = blockIdx.y * BM;
    int gn = blockIdx.x * BN;

    int am = t >> 1, ak = (t & 1) * 8;
    int bk = t >> 3, bn = (t & 7) * 8;

    float acc[8][4];
#pragma unroll
    for (int i = 0; i < 8; i++)
#pragma unroll
        for (int j = 0; j < 4; j++) acc[i][j] = 0.0f;

    for (int k0 = 0; k0 < K; k0 += BK) {
        float4 a0, a1;
        int row = gm + am;
        if (row < M) {
            const float* ap = A + (size_t)row * K + k0 + ak;
            a0 = *(const float4*)ap;
            a1 = *(const float4*)(ap + 4);
        } else {
            a0 = make_float4(0.f, 0.f, 0.f, 0.f);
            a1 = a0;
        }
        As[ak + 0][am] = a0.x; As[ak + 1][am] = a0.y;
        As[ak + 2][am] = a0.z; As[ak + 3][am] = a0.w;
        As[ak + 4][am] = a1.x; As[ak + 5][am] = a1.y;
        As[ak + 6][am] = a1.z; As[ak + 7][am] = a1.w;

        const float* wp = W + (size_t)(k0 + bk) * Nout + gn + bn;
        *(float4*)&Bs[bk][bn]     = *(const float4*)wp;
        *(float4*)&Bs[bk][bn + 4] = *(const float4*)(wp + 4);

        __syncthreads();
#pragma unroll
        for (int k = 0; k < BK; k++) {
            float a[8], b[4];
            *(float4*)&a[0] = *(const float4*)&As[k][ty * 8];
            *(float4*)&a[4] = *(const float4*)&As[k][ty * 8 + 4];
            *(float4*)&b[0] = *(const float4*)&Bs[k][tx * 4];
#pragma unroll
            for (int i = 0; i < 8; i++)
#pragma unroll
                for (int j = 0; j < 4; j++)
                    acc[i][j] = fmaf(a[i], b[j], acc[i][j]);
        }
        __syncthreads();
    }

    float4 bv = *(const float4*)(bias + gn + tx * 4);
#pragma unroll
    for (int i = 0; i < 8; i++) {
        int row = gm + ty * 8 + i;
        if (row < M) {
            float4 o;
            o.x = acc[i][0] + bv.x;
            o.y = acc[i][1] + bv.y;
            o.z = acc[i][2] + bv.z;
            o.w = acc[i][3] + bv.w;
            *(float4*)&C[(size_t)row * Nout + gn + tx * 4] = o;
        }
    }
}

// ---------------------------------------------------------------------------
extern "C" void kernel_launch(void* const* d_in, const int* in_sizes, int n_in,
                              void* d_out, int out_size) {
    const float* x    = (const float*)d_in[0];   // [N, 128]
    const int*   esrc = (const int*)  d_in[1];   // [R, E]
    const int*   edst = (const int*)  d_in[2];   // [R, E]
    const float* W0   = (const float*)d_in[3];   // [R, 128, 128]
    const float* b0   = (const float*)d_in[4];   // [R, 128]
    const float* Wl   = (const float*)d_in[5];   // [4, R, 128, 128]
    const float* bl   = (const float*)d_in[6];   // [4, R, 128]
    const float* Wout = (const float*)d_in[7];   // [128, 64]
    const float* bout = (const float*)d_in[8];   // [64]
    float* out = (float*)d_out;
    (void)in_sizes; (void)n_in; (void)out_size;

    void *degp, *yp, *hp, *rowp, *curp;
    cudaGetSymbolAddress(&degp, g_deg);
    cudaGetSymbolAddress(&yp,   g_Y);
    cudaGetSymbolAddress(&hp,   g_H);
    cudaGetSymbolAddress(&rowp, g_rowptr);
    cudaGetSymbolAddress(&curp, g_cursor);
    float* H0 = (float*)hp;
    float* H1 = H0 + (size_t)NNODES * DHID;
    float* Y  = (float*)yp;

    // ---- CSR build (once per launch) ----
    const int NBLK = (NW + 1023) / 1024;   // 147
    cudaMemsetAsync(degp, 0, sizeof(int) * 2 * NW, 0);
    deg_count_kernel<<<(NREL * NEDGE + 255) / 256, 256>>>(esrc, edst);
    deg_inv_kernel<<<(2 * NW + 255) / 256, 256>>>();
    scan1_kernel<<<NBLK, 256>>>();
    scan2_kernel<<<1, 256>>>(NBLK);
    scan3_kernel<<<(NW + 255) / 256, 256>>>();
    cudaMemcpyAsync(curp, rowp, sizeof(int) * NW, cudaMemcpyDeviceToDevice, 0);
    fill_kernel<<<(NREL * NEDGE + 255) / 256, 256>>>(esrc, edst);

    // ---- 5 layers: transform GEMM then CSR gather ----
    const float* hin = x;
    for (int l = 0; l < 5; l++) {
        const float* Wlayer = (l == 0) ? W0 : Wl + (size_t)(l - 1) * NREL * DHID * DHID;
        const float* blayer = (l == 0) ? b0 : bl + (size_t)(l - 1) * NREL * DHID;
        float* hout = (l & 1) ? H1 : H0;

        dim3 ggrid(NREL, (NNODES + GBM - 1) / GBM);
        gemm_transform<<<ggrid, 256>>>(hin, Wlayer, Y);

        long long nthreads = (long long)NNODES * 32;
        gather_kernel<<<(unsigned)((nthreads + 255) / 256), 256>>>(
            Y, blayer, (l < 4) ? 1 : 0, hout);

        hin = hout;
    }

    // ---- final linear 128 -> 64 ----
    dim3 fgrid(DOUT / BN, (NNODES + BM - 1) / BM);
    gemm_final<<<fgrid, 128>>>(hin, Wout, bout, NNODES, DHID, DOUT, out);
}

// round 11
// speedup vs baseline: 2.5367x; 1.4481x over previous
#include <cuda_runtime.h>
#include <cuda_bf16.h>
#include <cstdint>
#include <cstddef>

// ---------------------------------------------------------------------------
// RGCN, transform-then-gather per layer:
//   Y[n, r*128+j] = sum_k h[n,k] * W[r][k][j]     (bf16x3 mma.sync GEMM)
//   H'[dst, j]    = leaky((1/3)(sum_r sum_e scale_e * Y[src_e, r*128+j]) + bmean)
// CSR (dst-sorted + folded norms) built once per launch.
// GEMM precision: fp32 operands split into bf16 hi+lo; 3 accumulating passes
// (hi*hi + hi*lo + lo*hi) in fp32 accumulators -> ~2^-18 relative error.
// NOTE: tcgen05 is NOT available under this bench's compile target (plain
// sm_103); mma.sync m16n8k16 (sm_80+) is.
// ---------------------------------------------------------------------------

#define NNODES 50000
#define DHID   128
#define DOUT   64
#define NREL   3
#define NEDGE  800000
#define NW     (NREL * NNODES)
#define NEG_SLOPE 0.01f
#define NMTILE ((NNODES + 127) / 128)    // 391

// -------- static device scratch ---------------------------------------------
__device__ float g_H[2][(size_t)NNODES * DHID];
__device__ float g_Y[(size_t)NNODES * NREL * DHID];
__device__ int   g_deg[2 * NW];
__device__ float g_inv[2 * NW];
__device__ int   g_rowptr[NW + 1];
__device__ int   g_cursor[NW];
__device__ int   g_bsums[256];
__device__ int   g_csr_src[NREL * NEDGE];
__device__ float g_csr_scale[NREL * NEDGE];
// transposed + bf16-split weights: [5*3][n=128][k=128] (col-major B for mma)
__device__ __nv_bfloat16 g_Whi[15 * DHID * DHID];
__device__ __nv_bfloat16 g_Wlo[15 * DHID * DHID];

__device__ __forceinline__ uint32_t smem_u32(const void* p) {
    uint32_t a;
    asm("{ .reg .u64 t; cvta.to.shared.u64 t, %1; cvt.u32.u64 %0, t; }"
        : "=r"(a) : "l"(p));
    return a;
}
__device__ __forceinline__ uint32_t bfpair(__nv_bfloat16 a, __nv_bfloat16 b) {
    return (uint32_t)__bfloat16_as_ushort(a) | ((uint32_t)__bfloat16_as_ushort(b) << 16);
}

// ============================ CSR build =====================================
__global__ void deg_count_kernel(const int* __restrict__ esrc,
                                 const int* __restrict__ edst) {
    int i = blockIdx.x * blockDim.x + threadIdx.x;
    if (i >= NREL * NEDGE) return;
    int r = i / NEDGE;
    atomicAdd(&g_deg[r * NNODES + esrc[i]], 1);
    atomicAdd(&g_deg[NW + r * NNODES + edst[i]], 1);
}
__global__ void deg_inv_kernel() {
    int i = blockIdx.x * blockDim.x + threadIdx.x;
    if (i >= 2 * NW) return;
    g_inv[i] = rsqrtf(fmaxf((float)g_deg[i], 1.0f));
}
__global__ void scan1_kernel() {
    __shared__ int sh[256];
    int t = threadIdx.x;
    int base = blockIdx.x * 1024 + t * 4;
    int v[4], s = 0;
#pragma unroll
    for (int j = 0; j < 4; j++) {
        int idx = base + j;
        v[j] = (idx < NW) ? g_deg[NW + idx] : 0;
        s += v[j];
    }
    sh[t] = s;
    __syncthreads();
    for (int off = 1; off < 256; off <<= 1) {
        int x = (t >= off) ? sh[t - off] : 0;
        __syncthreads();
        sh[t] += x;
        __syncthreads();
    }
    int run = sh[t] - s;
#pragma unroll
    for (int j = 0; j < 4; j++) {
        int idx = base + j;
        if (idx < NW) g_rowptr[idx] = run;
        run += v[j];
    }
    if (t == 255) g_bsums[blockIdx.x] = sh[255];
}
__global__ void scan2_kernel(int nblocks) {
    __shared__ int sh[256];
    int t = threadIdx.x;
    int v = (t < nblocks) ? g_bsums[t] : 0;
    sh[t] = v;
    __syncthreads();
    for (int off = 1; off < 256; off <<= 1) {
        int x = (t >= off) ? sh[t - off] : 0;
        __syncthreads();
        sh[t] += x;
        __syncthreads();
    }
    if (t < nblocks) g_bsums[t] = sh[t] - v;
    if (t == 255) g_rowptr[NW] = sh[255];
}
__global__ void scan3_kernel() {
    int i = blockIdx.x * blockDim.x + threadIdx.x;
    if (i >= NW) return;
    g_rowptr[i] += g_bsums[i >> 10];
}
__global__ void fill_kernel(const int* __restrict__ esrc,
                            const int* __restrict__ edst) {
    int i = blockIdx.x * blockDim.x + threadIdx.x;
    if (i >= NREL * NEDGE) return;
    int r = i / NEDGE;
    int src = esrc[i];
    int dst = edst[i];
    int w = r * NNODES + dst;
    int pos = atomicAdd(&g_cursor[w], 1);
    g_csr_src[pos]   = src;
    g_csr_scale[pos] = g_inv[r * NNODES + src] * g_inv[NW + w];
}

// ================= W transpose + bf16 split (once per launch) ===============
// g_W{hi,lo}[lr][n][k] = split( W_lr[k][n] );  lr = layer*3 + r
__global__ void wprep_kernel(const float* __restrict__ W0,
                             const float* __restrict__ Wl) {
    int i = blockIdx.x * blockDim.x + threadIdx.x;
    if (i >= 15 * DHID * DHID) return;
    int k  = i & 127;
    int n  = (i >> 7) & 127;
    int lr = i >> 14;
    const float* src = (lr < 3) ? (W0 + (size_t)lr * DHID * DHID)
                                : (Wl + (size_t)(lr - 3) * DHID * DHID);
    float v = src[(size_t)k * DHID + n];
    __nv_bfloat16 hi = __float2bfloat16(v);
    __nv_bfloat16 lo = __float2bfloat16(v - __bfloat162float(hi));
    size_t o = (size_t)lr * DHID * DHID + (size_t)n * DHID + k;
    g_Whi[o] = hi;
    g_Wlo[o] = lo;
}

// =================== bf16x3 mma.sync transform GEMM =========================
// grid (NREL, NMTILE), 256 threads (8 warps as 4m x 2n; warp tile 32x64).
// Per CTA: Y[128, r*128 +: 128] = A_tile[128,128] @ Wr^T, K chunked by 32.
#define KCH  32
#define LDA  40                 // padded SMEM k-stride (bf16 elems; 80B rows)

__device__ __forceinline__ void ldm_x4(uint32_t* r, uint32_t addr) {
    asm volatile("ldmatrix.sync.aligned.m8n8.x4.shared.b16 {%0,%1,%2,%3}, [%4];"
                 : "=r"(r[0]), "=r"(r[1]), "=r"(r[2]), "=r"(r[3]) : "r"(addr));
}
__device__ __forceinline__ void mma_bf16(float* c, const uint32_t* a,
                                         const uint32_t* b) {
    asm volatile(
        "mma.sync.aligned.m16n8k16.row.col.f32.bf16.bf16.f32 "
        "{%0,%1,%2,%3}, {%4,%5,%6,%7}, {%8,%9}, {%0,%1,%2,%3};"
        : "+f"(c[0]), "+f"(c[1]), "+f"(c[2]), "+f"(c[3])
        : "r"(a[0]), "r"(a[1]), "r"(a[2]), "r"(a[3]), "r"(b[0]), "r"(b[1]));
}

__global__ __launch_bounds__(256)
void gemm_bf16x3(const float* __restrict__ A,            // [NNODES, 128]
                 const __nv_bfloat16* __restrict__ Whi,  // [15][128][128]
                 const __nv_bfloat16* __restrict__ Wlo,
                 int lr_base,
                 float* __restrict__ Y) {                // [NNODES, 384]
    __shared__ __nv_bfloat16 Ah[128 * LDA];
    __shared__ __nv_bfloat16 Al[128 * LDA];
    __shared__ __nv_bfloat16 Bh[128 * LDA];
    __shared__ __nv_bfloat16 Bl[128 * LDA];

    const int t    = threadIdx.x;
    const int lane = t & 31;
    const int wid  = t >> 5;
    const int rrel = blockIdx.x;
    const int gm   = blockIdx.y * 128;
    const int warp_m = (wid >> 1) * 32;
    const int warp_n = (wid & 1) * 64;

    const __nv_bfloat16* wh = Whi + (size_t)(lr_base + rrel) * DHID * DHID;
    const __nv_bfloat16* wl = Wlo + (size_t)(lr_base + rrel) * DHID * DHID;

    float acc[2][8][4];
#pragma unroll
    for (int mi = 0; mi < 2; mi++)
#pragma unroll
        for (int nj = 0; nj < 8; nj++)
#pragma unroll
            for (int q = 0; q < 4; q++) acc[mi][nj][q] = 0.0f;

    // ldmatrix per-lane address components
    const int arow  = lane & 15;          // A: lanes 0-15 rows, 16-31 rows @k+8
    const int akoff = (lane >> 4) * 8;
    const int bnadd = (lane & 7) + ((lane >> 4) * 8);  // B: g>=2 -> +8 n rows
    const int bkadd = ((lane >> 3) & 1) * 8;

    const uint32_t ah_base = smem_u32(Ah);
    const uint32_t al_base = smem_u32(Al);
    const uint32_t bh_base = smem_u32(Bh);
    const uint32_t bl_base = smem_u32(Bl);

    for (int k0 = 0; k0 < DHID; k0 += KCH) {
        if (k0) __syncthreads();   // protect SMEM reuse
        // ---- stage A chunk (fp32 -> bf16 hi/lo), rows 0..127, k0..k0+31 ----
#pragma unroll
        for (int it = 0; it < 4; it++) {
            int q   = t + it * 256;          // 0..1023
            int row = q >> 3;
            int kq  = (q & 7) * 4;
            float4 v;
            int grow = gm + row;
            if (grow < NNODES) v = *(const float4*)(A + (size_t)grow * DHID + k0 + kq);
            else               v = make_float4(0.f, 0.f, 0.f, 0.f);
            __nv_bfloat16 h0 = __float2bfloat16(v.x), h1 = __float2bfloat16(v.y);
            __nv_bfloat16 h2 = __float2bfloat16(v.z), h3 = __float2bfloat16(v.w);
            __nv_bfloat16 l0 = __float2bfloat16(v.x - __bfloat162float(h0));
            __nv_bfloat16 l1 = __float2bfloat16(v.y - __bfloat162float(h1));
            __nv_bfloat16 l2 = __float2bfloat16(v.z - __bfloat162float(h2));
            __nv_bfloat16 l3 = __float2bfloat16(v.w - __bfloat162float(h3));
            int idx = row * LDA + kq;
            *(uint2*)&Ah[idx] = make_uint2(bfpair(h0, h1), bfpair(h2, h3));
            *(uint2*)&Al[idx] = make_uint2(bfpair(l0, l1), bfpair(l2, l3));
        }
        // ---- stage B chunk: [n][k0..k0+31] bf16 from global ----
#pragma unroll
        for (int it = 0; it < 2; it++) {
            int q  = t + it * 256;           // 0..511
            int n  = q >> 2;
            int kq = (q & 3) * 8;
            int idx = n * LDA + kq;
            *(uint4*)&Bh[idx] = *(const uint4*)(wh + (size_t)n * DHID + k0 + kq);
            *(uint4*)&Bl[idx] = *(const uint4*)(wl + (size_t)n * DHID + k0 + kq);
        }
        __syncthreads();

        // ---- 2 k-steps of 16 per chunk ----
#pragma unroll
        for (int ks = 0; ks < 2; ks++) {
            int k = ks * 16;
            uint32_t ah[2][4], al[2][4], bh[8][2], bl[8][2];
#pragma unroll
            for (int mi = 0; mi < 2; mi++) {
                uint32_t off = (uint32_t)((warp_m + mi * 16 + arow) * LDA
                                          + k + akoff) * 2;
                ldm_x4(ah[mi], ah_base + off);
                ldm_x4(al[mi], al_base + off);
            }
#pragma unroll
            for (int j = 0; j < 4; j++) {    // ntile pairs (2j, 2j+1)
                uint32_t off = (uint32_t)((warp_n + j * 16 + bnadd) * LDA
                                          + k + bkadd) * 2;
                uint32_t rh[4], rl[4];
                ldm_x4(rh, bh_base + off);
                ldm_x4(rl, bl_base + off);
                bh[2 * j][0] = rh[0]; bh[2 * j][1] = rh[1];
                bh[2 * j + 1][0] = rh[2]; bh[2 * j + 1][1] = rh[3];
                bl[2 * j][0] = rl[0]; bl[2 * j][1] = rl[1];
                bl[2 * j + 1][0] = rl[2]; bl[2 * j + 1][1] = rl[3];
            }
            // 3 passes: hi*hi, hi*lo, lo*hi
#pragma unroll
            for (int mi = 0; mi < 2; mi++)
#pragma unroll
                for (int nj = 0; nj < 8; nj++)
                    mma_bf16(acc[mi][nj], ah[mi], bh[nj]);
#pragma unroll
            for (int mi = 0; mi < 2; mi++)
#pragma unroll
                for (int nj = 0; nj < 8; nj++)
                    mma_bf16(acc[mi][nj], ah[mi], bl[nj]);
#pragma unroll
            for (int mi = 0; mi < 2; mi++)
#pragma unroll
                for (int nj = 0; nj < 8; nj++)
                    mma_bf16(acc[mi][nj], al[mi], bh[nj]);
        }
    }

    // ---- epilogue: c0,c1 -> (row g, col 2t,2t+1); c2,c3 -> row g+8 ----
    const int g  = lane >> 2;
    const int tt = lane & 3;
#pragma unroll
    for (int mi = 0; mi < 2; mi++) {
        int row0 = gm + warp_m + mi * 16 + g;
        int row1 = row0 + 8;
#pragma unroll
        for (int nj = 0; nj < 8; nj++) {
            int col = warp_n + nj * 8 + tt * 2;
            if (row0 < NNODES)
                *(float2*)(Y + (size_t)row0 * (NREL * DHID) + rrel * DHID + col)
                    = make_float2(acc[mi][nj][0], acc[mi][nj][1]);
            if (row1 < NNODES)
                *(float2*)(Y + (size_t)row1 * (NREL * DHID) + rrel * DHID + col)
                    = make_float2(acc[mi][nj][2], acc[mi][nj][3]);
        }
    }
}

// ============================ CSR gather ====================================
__global__ __launch_bounds__(256)
void gather_kernel(const float* __restrict__ Y,
                   const float* __restrict__ bias,  // [R, 128]
                   int act,
                   float* __restrict__ Hout) {
    int w    = (blockIdx.x * blockDim.x + threadIdx.x) >> 5;
    int lane = threadIdx.x & 31;
    if (w >= NNODES) return;

    float4 acc = make_float4(0.f, 0.f, 0.f, 0.f);
#pragma unroll
    for (int r = 0; r < NREL; r++) {
        int row = r * NNODES + w;
        int e   = g_rowptr[row];
        int end = g_rowptr[row + 1];
        const float* Ybase = Y + r * DHID + lane * 4;
        for (; e + 1 < end; e += 2) {
            int   s0 = g_csr_src[e],   s1 = g_csr_src[e + 1];
            float c0 = g_csr_scale[e], c1 = g_csr_scale[e + 1];
            float4 v0 = *(const float4*)(Ybase + (size_t)s0 * (NREL * DHID));
            float4 v1 = *(const float4*)(Ybase + (size_t)s1 * (NREL * DHID));
            acc.x = fmaf(c0, v0.x, acc.x); acc.y = fmaf(c0, v0.y, acc.y);
            acc.z = fmaf(c0, v0.z, acc.z); acc.w = fmaf(c0, v0.w, acc.w);
            acc.x = fmaf(c1, v1.x, acc.x); acc.y = fmaf(c1, v1.y, acc.y);
            acc.z = fmaf(c1, v1.z, acc.z); acc.w = fmaf(c1, v1.w, acc.w);
        }
        if (e < end) {
            int   s0 = g_csr_src[e];
            float c0 = g_csr_scale[e];
            float4 v0 = *(const float4*)(Ybase + (size_t)s0 * (NREL * DHID));
            acc.x = fmaf(c0, v0.x, acc.x); acc.y = fmaf(c0, v0.y, acc.y);
            acc.z = fmaf(c0, v0.z, acc.z); acc.w = fmaf(c0, v0.w, acc.w);
        }
    }
    float4 bm = make_float4(0.f, 0.f, 0.f, 0.f);
#pragma unroll
    for (int r = 0; r < NREL; r++) {
        float4 b = *(const float4*)(bias + r * DHID + lane * 4);
        bm.x += b.x; bm.y += b.y; bm.z += b.z; bm.w += b.w;
    }
    const float inv3 = 1.0f / NREL;
    float4 o;
    o.x = (acc.x + bm.x) * inv3;
    o.y = (acc.y + bm.y) * inv3;
    o.z = (acc.z + bm.z) * inv3;
    o.w = (acc.w + bm.w) * inv3;
    if (act) {
        o.x = o.x > 0.f ? o.x : o.x * NEG_SLOPE;
        o.y = o.y > 0.f ? o.y : o.y * NEG_SLOPE;
        o.z = o.z > 0.f ? o.z : o.z * NEG_SLOPE;
        o.w = o.w > 0.f ? o.w : o.w * NEG_SLOPE;
    }
    *(float4*)(Hout + (size_t)w * DHID + lane * 4) = o;
}

// ================= final 128->64 linear (SIMT fp32) =========================
#define BM 64
#define BN 64
#define BK 16
__global__ __launch_bounds__(128)
void gemm_final(const float* __restrict__ A, const float* __restrict__ W,
                const float* __restrict__ bias, int M, int K, int Nout,
                float* __restrict__ C) {
    __shared__ float As[BK][BM];
    __shared__ float Bs[BK][BN];
    int t  = threadIdx.x;
    int tx = t & 15, ty = t >> 4;
    int gm = blockIdx.y * BM, gn = blockIdx.x * BN;
    int am = t >> 1, ak = (t & 1) * 8;
    int bk = t >> 3, bn = (t & 7) * 8;

    float acc[8][4];
#pragma unroll
    for (int i = 0; i < 8; i++)
#pragma unroll
        for (int j = 0; j < 4; j++) acc[i][j] = 0.0f;

    for (int k0 = 0; k0 < K; k0 += BK) {
        float4 a0, a1;
        int row = gm + am;
        if (row < M) {
            const float* ap = A + (size_t)row * K + k0 + ak;
            a0 = *(const float4*)ap;
            a1 = *(const float4*)(ap + 4);
        } else {
            a0 = make_float4(0.f, 0.f, 0.f, 0.f);
            a1 = a0;
        }
        As[ak + 0][am] = a0.x; As[ak + 1][am] = a0.y;
        As[ak + 2][am] = a0.z; As[ak + 3][am] = a0.w;
        As[ak + 4][am] = a1.x; As[ak + 5][am] = a1.y;
        As[ak + 6][am] = a1.z; As[ak + 7][am] = a1.w;
        const float* wp = W + (size_t)(k0 + bk) * Nout + gn + bn;
        *(float4*)&Bs[bk][bn]     = *(const float4*)wp;
        *(float4*)&Bs[bk][bn + 4] = *(const float4*)(wp + 4);
        __syncthreads();
#pragma unroll
        for (int k = 0; k < BK; k++) {
            float a[8], b[4];
            *(float4*)&a[0] = *(const float4*)&As[k][ty * 8];
            *(float4*)&a[4] = *(const float4*)&As[k][ty * 8 + 4];
            *(float4*)&b[0] = *(const float4*)&Bs[k][tx * 4];
#pragma unroll
            for (int i = 0; i < 8; i++)
#pragma unroll
                for (int j = 0; j < 4; j++)
                    acc[i][j] = fmaf(a[i], b[j], acc[i][j]);
        }
        __syncthreads();
    }
    float4 bv = *(const float4*)(bias + gn + tx * 4);
#pragma unroll
    for (int i = 0; i < 8; i++) {
        int row = gm + ty * 8 + i;
        if (row < M) {
            float4 o;
            o.x = acc[i][0] + bv.x; o.y = acc[i][1] + bv.y;
            o.z = acc[i][2] + bv.z; o.w = acc[i][3] + bv.w;
            *(float4*)&C[(size_t)row * Nout + gn + tx * 4] = o;
        }
    }
}

// ---------------------------------------------------------------------------
extern "C" void kernel_launch(void* const* d_in, const int* in_sizes, int n_in,
                              void* d_out, int out_size) {
    const float* x    = (const float*)d_in[0];
    const int*   esrc = (const int*)  d_in[1];
    const int*   edst = (const int*)  d_in[2];
    const float* W0   = (const float*)d_in[3];
    const float* b0   = (const float*)d_in[4];
    const float* Wl   = (const float*)d_in[5];
    const float* bl   = (const float*)d_in[6];
    const float* Wout = (const float*)d_in[7];
    const float* bout = (const float*)d_in[8];
    float* out = (float*)d_out;
    (void)in_sizes; (void)n_in; (void)out_size;

    void *degp, *yp, *hp, *rowp, *curp, *whip, *wlop;
    cudaGetSymbolAddress(&degp, g_deg);
    cudaGetSymbolAddress(&yp,   g_Y);
    cudaGetSymbolAddress(&hp,   g_H);
    cudaGetSymbolAddress(&rowp, g_rowptr);
    cudaGetSymbolAddress(&curp, g_cursor);
    cudaGetSymbolAddress(&whip, g_Whi);
    cudaGetSymbolAddress(&wlop, g_Wlo);
    float* H0 = (float*)hp;
    float* H1 = H0 + (size_t)NNODES * DHID;
    float* Y  = (float*)yp;
    const __nv_bfloat16* Whi = (const __nv_bfloat16*)whip;
    const __nv_bfloat16* Wlo = (const __nv_bfloat16*)wlop;

    // ---- weight prep + CSR build (once per launch) ----
    wprep_kernel<<<(15 * DHID * DHID + 255) / 256, 256>>>(W0, Wl);
    const int NBLK = (NW + 1023) / 1024;
    cudaMemsetAsync(degp, 0, sizeof(int) * 2 * NW, 0);
    deg_count_kernel<<<(NREL * NEDGE + 255) / 256, 256>>>(esrc, edst);
    deg_inv_kernel<<<(2 * NW + 255) / 256, 256>>>();
    scan1_kernel<<<NBLK, 256>>>();
    scan2_kernel<<<1, 256>>>(NBLK);
    scan3_kernel<<<(NW + 255) / 256, 256>>>();
    cudaMemcpyAsync(curp, rowp, sizeof(int) * NW, cudaMemcpyDeviceToDevice, 0);
    fill_kernel<<<(NREL * NEDGE + 255) / 256, 256>>>(esrc, edst);

    // ---- 5 layers: bf16x3 tensor GEMM then CSR gather ----
    const float* hin = x;
    for (int l = 0; l < 5; l++) {
        const float* blayer = (l == 0) ? b0 : bl + (size_t)(l - 1) * NREL * DHID;
        float* hout = (l & 1) ? H1 : H0;

        dim3 ggrid(NREL, NMTILE);
        gemm_bf16x3<<<ggrid, 256>>>(hin, Whi, Wlo, l * 3, Y);

        long long nthreads = (long long)NNODES * 32;
        gather_kernel<<<(unsigned)((nthreads + 255) / 256), 256>>>(
            Y, blayer, (l < 4) ? 1 : 0, hout);
        hin = hout;
    }

    // ---- final linear 128 -> 64 ----
    dim3 fgrid(DOUT / BN, (NNODES + BM - 1) / BM);
    gemm_final<<<fgrid, 128>>>(hin, Wout, bout, NNODES, DHID, DOUT, out);
}